// round 5
// baseline (speedup 1.0000x reference)
#include <cuda_runtime.h>
#include <math.h>

#define TT 512
#define BB 128
#define DD 128
#define HH 256
#define CC 10
#define G4 1024
#define MROWS (TT*BB)
#define NCTA 128

// ---------------- static device scratch (no runtime allocation) ----------------
__device__ float g_e  [(size_t)MROWS * DD];        //  32 MB embedded inputs [t*B+b, D]
__device__ float g_XwF[(size_t)MROWS * G4];        // 256 MB x@W fwd (reused layer 2)
__device__ float g_XwB[(size_t)MROWS * G4];        // 256 MB x@W bwd (reused layer 2)
__device__ float g_seq[(size_t)MROWS * 2 * HH];    // 128 MB layer-1 output sequence
__device__ float g_state[4 * BB * HH];             // per dir: h parity buf0, buf1
__device__ unsigned g_flags[NCTA * 32];            // barrier flags, 1 per 128B line

// packed dual-fp32 FMA - 2x throughput of scalar 3-reg FFMA on sm_103a
__device__ __forceinline__ void ffma2(float2 &d, float2 a, float2 b) {
    asm("fma.rn.f32x2 %0, %1, %2, %0;"
        : "+l"(*reinterpret_cast<unsigned long long*>(&d))
        : "l"(*reinterpret_cast<unsigned long long*>(&a)),
          "l"(*reinterpret_cast<unsigned long long*>(&b)));
}

__device__ __forceinline__ float sigf(float x) {
    return __fdividef(1.0f, 1.0f + __expf(-x));
}
__device__ __forceinline__ float tanhfast(float x) {
    return __fdividef(2.0f, 1.0f + __expf(-2.0f * x)) - 1.0f;
}

// atomic-free grid barrier: CTA b publishes monotonically increasing epoch in
// g_flags[b*32]; thread i spins on CTA i's flag (parallel L2 loads, no LTS
// atomic serialization). All NCTA CTAs are co-resident (1 per SM).
__device__ __forceinline__ void grid_bar(unsigned target) {
    __syncthreads();
    __threadfence();                                   // release my data stores
    if (threadIdx.x == 0)
        *(volatile unsigned*)&g_flags[blockIdx.x * 32] = target;
    {
        volatile unsigned* f = &g_flags[threadIdx.x * 32];   // blockDim == NCTA
        while (*f < target) { }
    }
    __threadfence();                                   // acquire before consuming
    __syncthreads();
}

// ---------------- embedding gather: g_e[t*B+b, :] = emb[x[b,t], :] ----------------
__global__ void embed_k(const int* __restrict__ x, const float* __restrict__ emb) {
    int gid = blockIdx.x * blockDim.x + threadIdx.x;
    int r  = gid >> 5;
    int c4 = gid & 31;
    int t  = r >> 7;
    int b  = r & 127;
    int tok = x[b * TT + t];
    reinterpret_cast<float4*>(g_e)[(size_t)r * 32 + c4] =
        reinterpret_cast<const float4*>(emb)[(size_t)tok * 32 + c4];
}

// ---------------- SGEMM + bias: C[M,1024] = A[M,K] @ W[K,1024] + bias ----------------
// BM=128 BN=128 BK=16, 256 threads, 8x8/thread, double-buffered smem, 1 sync/tile
__global__ __launch_bounds__(256, 2) void gemm_k(int a_sel, int c_sel,
        const float* __restrict__ W, const float* __restrict__ bias, int K)
{
    const float* A = a_sel ? g_seq : g_e;
    float*       C = c_sel ? g_XwB : g_XwF;

    __shared__ __align__(16) float As[2][16][132];   // [buf][k][m]
    __shared__ __align__(16) float Bs[2][16][132];   // [buf][k][n]

    const int m0  = blockIdx.x * 128;
    const int n0  = blockIdx.y * 128;
    const int tid = threadIdx.x;
    const int ty  = tid >> 4;
    const int tx  = tid & 15;

    // load coords: 2 float4 per thread for each of A and B per 16-k tile
    const int ar  = tid >> 2;          // A rows: ar, ar+64
    const int akq = tid & 3;           // A k-quad
    const int br  = tid >> 5;          // B k-rows: br, br+8
    const int bc  = (tid & 31) * 4;    // B col float4

    float2 acc[8][4];
#pragma unroll
    for (int i = 0; i < 8; ++i)
#pragma unroll
        for (int j = 0; j < 4; ++j) acc[i][j] = make_float2(0.f, 0.f);

    const int nk = K >> 4;

    // prologue: tile 0 -> buf 0
    {
        float4 a0 = *reinterpret_cast<const float4*>(A + (size_t)(m0 + ar)      * K + akq * 4);
        float4 a1 = *reinterpret_cast<const float4*>(A + (size_t)(m0 + ar + 64) * K + akq * 4);
        float4 b0 = *reinterpret_cast<const float4*>(W + (size_t)br       * G4 + n0 + bc);
        float4 b1 = *reinterpret_cast<const float4*>(W + (size_t)(br + 8) * G4 + n0 + bc);
        As[0][akq * 4 + 0][ar] = a0.x; As[0][akq * 4 + 1][ar] = a0.y;
        As[0][akq * 4 + 2][ar] = a0.z; As[0][akq * 4 + 3][ar] = a0.w;
        As[0][akq * 4 + 0][ar + 64] = a1.x; As[0][akq * 4 + 1][ar + 64] = a1.y;
        As[0][akq * 4 + 2][ar + 64] = a1.z; As[0][akq * 4 + 3][ar + 64] = a1.w;
        *reinterpret_cast<float4*>(&Bs[0][br][bc])     = b0;
        *reinterpret_cast<float4*>(&Bs[0][br + 8][bc]) = b1;
    }
    __syncthreads();

    for (int kt = 0; kt < nk; ++kt) {
        const int cur = kt & 1;
        const bool more = (kt + 1) < nk;
        float4 a0, a1, b0, b1;
        if (more) {
            const int kb = (kt + 1) << 4;
            a0 = *reinterpret_cast<const float4*>(A + (size_t)(m0 + ar)      * K + kb + akq * 4);
            a1 = *reinterpret_cast<const float4*>(A + (size_t)(m0 + ar + 64) * K + kb + akq * 4);
            b0 = *reinterpret_cast<const float4*>(W + (size_t)(kb + br)     * G4 + n0 + bc);
            b1 = *reinterpret_cast<const float4*>(W + (size_t)(kb + br + 8) * G4 + n0 + bc);
        }
#pragma unroll
        for (int k = 0; k < 16; ++k) {
            float4 av0 = *reinterpret_cast<const float4*>(&As[cur][k][ty * 8]);
            float4 av1 = *reinterpret_cast<const float4*>(&As[cur][k][ty * 8 + 4]);
            float4 bv0 = *reinterpret_cast<const float4*>(&Bs[cur][k][tx * 8]);
            float4 bv1 = *reinterpret_cast<const float4*>(&Bs[cur][k][tx * 8 + 4]);
            float av8[8] = {av0.x, av0.y, av0.z, av0.w, av1.x, av1.y, av1.z, av1.w};
            float2 bp[4] = {{bv0.x, bv0.y}, {bv0.z, bv0.w}, {bv1.x, bv1.y}, {bv1.z, bv1.w}};
#pragma unroll
            for (int i = 0; i < 8; ++i) {
                float2 aa = make_float2(av8[i], av8[i]);
#pragma unroll
                for (int j = 0; j < 4; ++j) ffma2(acc[i][j], aa, bp[j]);
            }
        }
        if (more) {
            const int nxt = cur ^ 1;
            As[nxt][akq * 4 + 0][ar] = a0.x; As[nxt][akq * 4 + 1][ar] = a0.y;
            As[nxt][akq * 4 + 2][ar] = a0.z; As[nxt][akq * 4 + 3][ar] = a0.w;
            As[nxt][akq * 4 + 0][ar + 64] = a1.x; As[nxt][akq * 4 + 1][ar + 64] = a1.y;
            As[nxt][akq * 4 + 2][ar + 64] = a1.z; As[nxt][akq * 4 + 3][ar + 64] = a1.w;
            *reinterpret_cast<float4*>(&Bs[nxt][br][bc])     = b0;
            *reinterpret_cast<float4*>(&Bs[nxt][br + 8][bc]) = b1;
            __syncthreads();
        }
    }

    float4 bb0 = *reinterpret_cast<const float4*>(bias + n0 + tx * 8);
    float4 bb1 = *reinterpret_cast<const float4*>(bias + n0 + tx * 8 + 4);
#pragma unroll
    for (int i = 0; i < 8; ++i) {
        size_t row = (size_t)(m0 + ty * 8 + i) * G4 + n0 + tx * 8;
        float4 o0 = make_float4(acc[i][0].x + bb0.x, acc[i][0].y + bb0.y,
                                acc[i][1].x + bb0.z, acc[i][1].y + bb0.w);
        float4 o1 = make_float4(acc[i][2].x + bb1.x, acc[i][2].y + bb1.y,
                                acc[i][3].x + bb1.z, acc[i][3].y + bb1.w);
        *reinterpret_cast<float4*>(C + row)     = o0;
        *reinterpret_cast<float4*>(C + row + 4) = o1;
    }
}

// ---------------- persistent bidirectional LSTM layer ----------------
__global__ __launch_bounds__(128) void lstm_persist_k(
        const float* __restrict__ Uf, const float* __restrict__ Ub, int write_seq)
{
    extern __shared__ float Us[];                 // [256][128] U slice
    __shared__ __align__(16) float sh[16][260];   // h tile stage

    const int bid = blockIdx.x;
    const int dir = bid >> 6;
    const int nt  = (bid >> 3) & 7;
    const int bt  = bid & 7;
    const int tid = threadIdx.x;

    const float* U  = dir ? Ub : Uf;
    const float* Xw = dir ? g_XwB : g_XwF;
    float* hbuf = g_state + (size_t)dir * 2 * BB * HH;

    // starting epoch: all flags are equal at kernel entry
    unsigned target = *(volatile unsigned*)&g_flags[bid * 32] + 1;

    // load U slice: Us[k*128 + g*32 + ln] = U[k*G4 + g*HH + nt*32 + ln]
    for (int i = tid; i < 256 * 32; i += 128) {
        int k = i >> 5;
        int col = (i & 31) * 4;
        int g = col >> 5, ln = col & 31;
        *reinterpret_cast<float4*>(&Us[k * 128 + col]) =
            *reinterpret_cast<const float4*>(U + (size_t)k * G4 + g * HH + nt * 32 + ln);
    }

    // zero my (bt, nt) patch of both h parity buffers
    for (int i = tid; i < 512; i += 128) {
        int r  = bt * 16 + (i >> 5);
        int cc = nt * 32 + (i & 31);
        __stcg(hbuf + (size_t)r * HH + cc, 0.f);
        __stcg(hbuf + (size_t)BB * HH + (size_t)r * HH + cc, 0.f);
    }

    grid_bar(target); ++target;

    const int b_half = tid >> 4;
    const int n_grp  = tid & 15;
    const int nloc   = n_grp * 2;
    const int ngl    = nt * 32 + nloc;
    const int r0     = bt * 16 + b_half * 2;

    float2 cst[2] = {make_float2(0.f, 0.f), make_float2(0.f, 0.f)};

    for (int s = 0; s < TT; ++s) {
        const int t   = dir ? (TT - 1 - s) : s;
        const int par = s & 1;
        const float* hRead  = hbuf + (size_t)par * BB * HH;
        float*       hWrite = hbuf + (size_t)(par ^ 1) * BB * HH;

        // stage h tile (16 rows x 256) from L2
#pragma unroll
        for (int i = 0; i < 8; ++i) {
            int f = tid + i * 128;
            int r = f >> 6, cq = f & 63;
            *reinterpret_cast<float4*>(&sh[r][cq * 4]) =
                __ldcg(reinterpret_cast<const float4*>(
                    hRead + (size_t)(bt * 16 + r) * HH + cq * 4));
        }
        const float* xw0 = Xw + ((size_t)t * BB + r0) * G4 + ngl;
        const float* xw1 = xw0 + G4;
        float2 x0[4], x1[4];
#pragma unroll
        for (int g = 0; g < 4; ++g) {
            x0[g] = *reinterpret_cast<const float2*>(xw0 + g * HH);
            x1[g] = *reinterpret_cast<const float2*>(xw1 + g * HH);
        }
        __syncthreads();

        float2 acc[4][2];
#pragma unroll
        for (int g = 0; g < 4; ++g) {
            acc[g][0] = make_float2(0.f, 0.f);
            acc[g][1] = make_float2(0.f, 0.f);
        }

        const float* sr0 = sh[b_half * 2];
        const float* sr1 = sh[b_half * 2 + 1];
        const float* Up  = Us + nloc;

#pragma unroll 4
        for (int k4 = 0; k4 < HH; k4 += 4) {
            float4 h0v = *reinterpret_cast<const float4*>(sr0 + k4);
            float4 h1v = *reinterpret_cast<const float4*>(sr1 + k4);
            const float h0a[4] = {h0v.x, h0v.y, h0v.z, h0v.w};
            const float h1a[4] = {h1v.x, h1v.y, h1v.z, h1v.w};
#pragma unroll
            for (int kk = 0; kk < 4; ++kk) {
                const float* row = Up + (size_t)(k4 + kk) * 128;
                float2 hh0 = make_float2(h0a[kk], h0a[kk]);
                float2 hh1 = make_float2(h1a[kk], h1a[kk]);
#pragma unroll
                for (int g = 0; g < 4; ++g) {
                    float2 u2 = *reinterpret_cast<const float2*>(row + g * 32);
                    ffma2(acc[g][0], u2, hh0);
                    ffma2(acc[g][1], u2, hh1);
                }
            }
        }

#pragma unroll
        for (int bb = 0; bb < 2; ++bb) {
            const float2* xg = bb ? x1 : x0;
            float zi0 = acc[0][bb].x + xg[0].x, zi1 = acc[0][bb].y + xg[0].y;
            float zf0 = acc[1][bb].x + xg[1].x, zf1 = acc[1][bb].y + xg[1].y;
            float zg0 = acc[2][bb].x + xg[2].x, zg1 = acc[2][bb].y + xg[2].y;
            float zo0 = acc[3][bb].x + xg[3].x, zo1 = acc[3][bb].y + xg[3].y;
            float c0 = sigf(zf0) * cst[bb].x + sigf(zi0) * tanhfast(zg0);
            float c1 = sigf(zf1) * cst[bb].y + sigf(zi1) * tanhfast(zg1);
            cst[bb] = make_float2(c0, c1);
            float h0 = sigf(zo0) * tanhfast(c0);
            float h1 = sigf(zo1) * tanhfast(c1);
            int r = r0 + bb;
            __stcg(reinterpret_cast<float2*>(hWrite + (size_t)r * HH + ngl),
                   make_float2(h0, h1));
            if (write_seq)
                *reinterpret_cast<float2*>(
                    g_seq + ((size_t)t * BB + r) * (2 * HH) + dir * HH + nloc + nt * 32) =
                    make_float2(h0, h1);
        }

        grid_bar(target); ++target;
    }
}

// ---------------- final dense + softmax ----------------
__global__ void final_k(const float* __restrict__ Wd, const float* __restrict__ bd,
                        float* __restrict__ out)
{
    int b = blockIdx.x, lane = threadIdx.x;
    const float* hf = g_state;
    const float* hb = g_state + 2 * BB * HH;
    float acc[CC];
#pragma unroll
    for (int c = 0; c < CC; ++c) acc[c] = 0.f;
    for (int k = lane; k < 2 * HH; k += 32) {
        float hv = (k < HH) ? hf[(size_t)b * HH + k] : hb[(size_t)b * HH + k - HH];
        const float* w = Wd + (size_t)k * CC;
#pragma unroll
        for (int c = 0; c < CC; ++c) acc[c] = fmaf(hv, w[c], acc[c]);
    }
#pragma unroll
    for (int c = 0; c < CC; ++c)
#pragma unroll
        for (int o = 16; o; o >>= 1) acc[c] += __shfl_down_sync(0xffffffffu, acc[c], o);
    if (lane == 0) {
        float m = -1e30f;
#pragma unroll
        for (int c = 0; c < CC; ++c) { acc[c] += bd[c]; m = fmaxf(m, acc[c]); }
        float e[CC], s = 0.f;
#pragma unroll
        for (int c = 0; c < CC; ++c) { e[c] = expf(acc[c] - m); s += e[c]; }
        float inv = 1.f / s;
#pragma unroll
        for (int c = 0; c < CC; ++c) out[b * CC + c] = e[c] * inv;
    }
}

extern "C" void kernel_launch(void* const* d_in, const int* in_sizes, int n_in,
                              void* d_out, int out_size)
{
    const int*   x   = (const int*)  d_in[0];
    const float* emb = (const float*)d_in[1];
    const float* W1f = (const float*)d_in[2];
    const float* U1f = (const float*)d_in[3];
    const float* b1f = (const float*)d_in[4];
    const float* W1b = (const float*)d_in[5];
    const float* U1b = (const float*)d_in[6];
    const float* b1b = (const float*)d_in[7];
    const float* W2f = (const float*)d_in[8];
    const float* U2f = (const float*)d_in[9];
    const float* b2f = (const float*)d_in[10];
    const float* W2b = (const float*)d_in[11];
    const float* U2b = (const float*)d_in[12];
    const float* b2b = (const float*)d_in[13];
    const float* Wd  = (const float*)d_in[14];
    const float* bd  = (const float*)d_in[15];
    float* out = (float*)d_out;

    static int smem_set = 0;
    if (!smem_set) {
        cudaFuncSetAttribute(lstm_persist_k,
                             cudaFuncAttributeMaxDynamicSharedMemorySize, 131072);
        smem_set = 1;
    }

    embed_k<<<(MROWS * 32) / 256, 256>>>(x, emb);

    dim3 gg(MROWS / 128, G4 / 128);

    // layer 1
    gemm_k<<<gg, 256>>>(0, 0, W1f, b1f, DD);
    gemm_k<<<gg, 256>>>(0, 1, W1b, b1b, DD);
    lstm_persist_k<<<NCTA, 128, 131072>>>(U1f, U1b, 1);

    // layer 2
    gemm_k<<<gg, 256>>>(1, 0, W2f, b2f, 2 * HH);
    gemm_k<<<gg, 256>>>(1, 1, W2b, b2b, 2 * HH);
    lstm_persist_k<<<NCTA, 128, 131072>>>(U2f, U2b, 0);

    final_k<<<BB, 32>>>(Wd, bd, out);
}

// round 6
// speedup vs baseline: 1.1184x; 1.1184x over previous
#include <cuda_runtime.h>
#include <math.h>

#define TT 512
#define BB 128
#define DD 128
#define HH 256
#define CC 10
#define G4 1024
#define MROWS (TT*BB)
#define NCTA 128

// ---------------- static device scratch (no runtime allocation) ----------------
__device__ float g_e  [(size_t)MROWS * DD];        //  32 MB embedded inputs [t*B+b, D]
__device__ float g_XwF[(size_t)MROWS * G4];        // 256 MB x@W fwd (reused layer 2)
__device__ float g_XwB[(size_t)MROWS * G4];        // 256 MB x@W bwd (reused layer 2)
__device__ float g_seq[(size_t)MROWS * 2 * HH];    // 128 MB layer-1 output sequence
__device__ float g_state[4 * BB * HH];             // per dir: h parity buf0, buf1
__device__ unsigned g_count;                       // grid barrier arrive counter
__device__ unsigned g_epoch;                       // grid barrier epoch

// packed dual-fp32 FMA - 2x throughput of scalar 3-reg FFMA on sm_103a
__device__ __forceinline__ void ffma2(float2 &d, float2 a, float2 b) {
    asm("fma.rn.f32x2 %0, %1, %2, %0;"
        : "+l"(*reinterpret_cast<unsigned long long*>(&d))
        : "l"(*reinterpret_cast<unsigned long long*>(&a)),
          "l"(*reinterpret_cast<unsigned long long*>(&b)));
}

__device__ __forceinline__ float sigf(float x) {
    return __fdividef(1.0f, 1.0f + __expf(-x));
}
__device__ __forceinline__ float tanhfast(float x) {
    return __fdividef(2.0f, 1.0f + __expf(-2.0f * x)) - 1.0f;
}

// cp.async 16B: GMEM -> SMEM without register staging (LDGSTS)
__device__ __forceinline__ void cpa16(unsigned dst, const void* src) {
    asm volatile("cp.async.cg.shared.global [%0], [%1], 16;" :: "r"(dst), "l"(src));
}
#define CPA_COMMIT() asm volatile("cp.async.commit_group;")
#define CPA_WAIT0()  asm volatile("cp.async.wait_group 0;")

// software grid barrier (R4 version: single atomic arrival, 1 spinner per CTA)
__device__ __forceinline__ void grid_bar(unsigned &epoch) {
    __threadfence();
    __syncthreads();
    if (threadIdx.x == 0) {
        if (atomicAdd(&g_count, 1) == NCTA - 1) {
            atomicExch(&g_count, 0);
            __threadfence();
            atomicAdd(&g_epoch, 1);
        } else {
            while (*(volatile unsigned*)&g_epoch == epoch) { }
        }
        epoch++;
    }
    __syncthreads();
}

// ---------------- embedding gather: g_e[t*B+b, :] = emb[x[b,t], :] ----------------
__global__ void embed_k(const int* __restrict__ x, const float* __restrict__ emb) {
    int gid = blockIdx.x * blockDim.x + threadIdx.x;
    int r  = gid >> 5;
    int c4 = gid & 31;
    int t  = r >> 7;
    int b  = r & 127;
    int tok = x[b * TT + t];
    reinterpret_cast<float4*>(g_e)[(size_t)r * 32 + c4] =
        reinterpret_cast<const float4*>(emb)[(size_t)tok * 32 + c4];
}

// ---------------- SGEMM + bias: C[M,1024] = A[M,K] @ W[K,1024] + bias ----------------
// BM=128 BN=128 BK=8, 256 threads, 8x8/thread, cp.async double-buffered smem.
__global__ __launch_bounds__(256) void gemm_k(int a_sel, int c_sel,
        const float* __restrict__ W, const float* __restrict__ bias, int K)
{
    const float* A = a_sel ? g_seq : g_e;
    float*       C = c_sel ? g_XwB : g_XwF;

    __shared__ __align__(16) float As[2][128][8];    // [buf][m][k] row-major (cp.async friendly)
    __shared__ __align__(16) float Bs[2][8][132];    // [buf][k][n] padded

    const int m0  = blockIdx.x * 128;
    const int n0  = blockIdx.y * 128;
    const int tid = threadIdx.x;
    const int ty  = tid >> 4;
    const int tx  = tid & 15;

    // cp.async coords: 1x16B of A and 1x16B of B per thread per tile
    const int ar  = tid >> 1;            // A row 0..127
    const int aq  = tid & 1;             // A k-half (float4)
    const int bkr = tid >> 5;            // B k-row 0..7
    const int bc  = (tid & 31) * 4;      // B col float4

    const unsigned sA = (unsigned)__cvta_generic_to_shared(&As[0][0][0]);
    const unsigned sB = (unsigned)__cvta_generic_to_shared(&Bs[0][0][0]);
    const unsigned dA = sA + (unsigned)(((ar) * 8 + aq * 4) * 4);
    const unsigned dB = sB + (unsigned)(((bkr) * 132 + bc) * 4);
    const unsigned bufA = 128 * 8 * 4;   // bytes per A buffer
    const unsigned bufB = 8 * 132 * 4;   // bytes per B buffer

    float2 acc[8][4];
#pragma unroll
    for (int i = 0; i < 8; ++i)
#pragma unroll
        for (int j = 0; j < 4; ++j) acc[i][j] = make_float2(0.f, 0.f);

    const int nk = K >> 3;

    // prologue: tile 0 -> buf 0
    cpa16(dA, A + (size_t)(m0 + ar) * K + aq * 4);
    cpa16(dB, W + (size_t)bkr * G4 + n0 + bc);
    CPA_COMMIT();
    CPA_WAIT0();
    __syncthreads();

    for (int kt = 0; kt < nk; ++kt) {
        const int cur = kt & 1;
        const bool more = (kt + 1) < nk;
        if (more) {
            const int kb = (kt + 1) << 3;
            const int nxt = cur ^ 1;
            cpa16(dA + nxt * bufA, A + (size_t)(m0 + ar) * K + kb + aq * 4);
            cpa16(dB + nxt * bufB, W + (size_t)(kb + bkr) * G4 + n0 + bc);
            CPA_COMMIT();
        }
#pragma unroll
        for (int k = 0; k < 8; ++k) {
            float4 bv0 = *reinterpret_cast<const float4*>(&Bs[cur][k][tx * 8]);
            float4 bv1 = *reinterpret_cast<const float4*>(&Bs[cur][k][tx * 8 + 4]);
            float2 bp[4] = {{bv0.x, bv0.y}, {bv0.z, bv0.w}, {bv1.x, bv1.y}, {bv1.z, bv1.w}};
#pragma unroll
            for (int i = 0; i < 8; ++i) {
                float a = As[cur][ty * 8 + i][k];
                float2 aa = make_float2(a, a);
#pragma unroll
                for (int j = 0; j < 4; ++j) ffma2(acc[i][j], aa, bp[j]);
            }
        }
        if (more) {
            CPA_WAIT0();
            __syncthreads();
        }
    }

    float4 bb0 = *reinterpret_cast<const float4*>(bias + n0 + tx * 8);
    float4 bb1 = *reinterpret_cast<const float4*>(bias + n0 + tx * 8 + 4);
#pragma unroll
    for (int i = 0; i < 8; ++i) {
        size_t row = (size_t)(m0 + ty * 8 + i) * G4 + n0 + tx * 8;
        float4 o0 = make_float4(acc[i][0].x + bb0.x, acc[i][0].y + bb0.y,
                                acc[i][1].x + bb0.z, acc[i][1].y + bb0.w);
        float4 o1 = make_float4(acc[i][2].x + bb1.x, acc[i][2].y + bb1.y,
                                acc[i][3].x + bb1.z, acc[i][3].y + bb1.w);
        *reinterpret_cast<float4*>(C + row)     = o0;
        *reinterpret_cast<float4*>(C + row + 4) = o1;
    }
}

// ---------------- persistent bidirectional LSTM layer (R4 version) ----------------
__global__ __launch_bounds__(128) void lstm_persist_k(
        const float* __restrict__ Uf, const float* __restrict__ Ub, int write_seq)
{
    extern __shared__ float Us[];                 // [256][128] U slice
    __shared__ __align__(16) float sh[16][260];   // h tile stage

    const int bid = blockIdx.x;
    const int dir = bid >> 6;
    const int nt  = (bid >> 3) & 7;
    const int bt  = bid & 7;
    const int tid = threadIdx.x;

    const float* U  = dir ? Ub : Uf;
    const float* Xw = dir ? g_XwB : g_XwF;
    float* hbuf = g_state + (size_t)dir * 2 * BB * HH;

    // load U slice: Us[k*128 + g*32 + ln] = U[k*G4 + g*HH + nt*32 + ln]
    for (int i = tid; i < 256 * 32; i += 128) {
        int k = i >> 5;
        int col = (i & 31) * 4;
        int g = col >> 5, ln = col & 31;
        *reinterpret_cast<float4*>(&Us[k * 128 + col]) =
            *reinterpret_cast<const float4*>(U + (size_t)k * G4 + g * HH + nt * 32 + ln);
    }

    // zero my (bt, nt) patch of both h parity buffers
    for (int i = tid; i < 512; i += 128) {
        int r  = bt * 16 + (i >> 5);
        int cc = nt * 32 + (i & 31);
        __stcg(hbuf + (size_t)r * HH + cc, 0.f);
        __stcg(hbuf + (size_t)BB * HH + (size_t)r * HH + cc, 0.f);
    }

    unsigned epoch = 0;
    if (tid == 0) epoch = *(volatile unsigned*)&g_epoch;
    grid_bar(epoch);

    const int b_half = tid >> 4;
    const int n_grp  = tid & 15;
    const int nloc   = n_grp * 2;
    const int ngl    = nt * 32 + nloc;
    const int r0     = bt * 16 + b_half * 2;

    float2 cst[2] = {make_float2(0.f, 0.f), make_float2(0.f, 0.f)};

    for (int s = 0; s < TT; ++s) {
        const int t   = dir ? (TT - 1 - s) : s;
        const int par = s & 1;
        const float* hRead  = hbuf + (size_t)par * BB * HH;
        float*       hWrite = hbuf + (size_t)(par ^ 1) * BB * HH;

#pragma unroll
        for (int i = 0; i < 8; ++i) {
            int f = tid + i * 128;
            int r = f >> 6, cq = f & 63;
            *reinterpret_cast<float4*>(&sh[r][cq * 4]) =
                __ldcg(reinterpret_cast<const float4*>(
                    hRead + (size_t)(bt * 16 + r) * HH + cq * 4));
        }
        const float* xw0 = Xw + ((size_t)t * BB + r0) * G4 + ngl;
        const float* xw1 = xw0 + G4;
        float2 x0[4], x1[4];
#pragma unroll
        for (int g = 0; g < 4; ++g) {
            x0[g] = *reinterpret_cast<const float2*>(xw0 + g * HH);
            x1[g] = *reinterpret_cast<const float2*>(xw1 + g * HH);
        }
        __syncthreads();

        float2 acc[4][2];
#pragma unroll
        for (int g = 0; g < 4; ++g) {
            acc[g][0] = make_float2(0.f, 0.f);
            acc[g][1] = make_float2(0.f, 0.f);
        }

        const float* sr0 = sh[b_half * 2];
        const float* sr1 = sh[b_half * 2 + 1];
        const float* Up  = Us + nloc;

#pragma unroll 4
        for (int k4 = 0; k4 < HH; k4 += 4) {
            float4 h0v = *reinterpret_cast<const float4*>(sr0 + k4);
            float4 h1v = *reinterpret_cast<const float4*>(sr1 + k4);
            const float h0a[4] = {h0v.x, h0v.y, h0v.z, h0v.w};
            const float h1a[4] = {h1v.x, h1v.y, h1v.z, h1v.w};
#pragma unroll
            for (int kk = 0; kk < 4; ++kk) {
                const float* row = Up + (size_t)(k4 + kk) * 128;
                float2 hh0 = make_float2(h0a[kk], h0a[kk]);
                float2 hh1 = make_float2(h1a[kk], h1a[kk]);
#pragma unroll
                for (int g = 0; g < 4; ++g) {
                    float2 u2 = *reinterpret_cast<const float2*>(row + g * 32);
                    ffma2(acc[g][0], u2, hh0);
                    ffma2(acc[g][1], u2, hh1);
                }
            }
        }

#pragma unroll
        for (int bb = 0; bb < 2; ++bb) {
            const float2* xg = bb ? x1 : x0;
            float zi0 = acc[0][bb].x + xg[0].x, zi1 = acc[0][bb].y + xg[0].y;
            float zf0 = acc[1][bb].x + xg[1].x, zf1 = acc[1][bb].y + xg[1].y;
            float zg0 = acc[2][bb].x + xg[2].x, zg1 = acc[2][bb].y + xg[2].y;
            float zo0 = acc[3][bb].x + xg[3].x, zo1 = acc[3][bb].y + xg[3].y;
            float c0 = sigf(zf0) * cst[bb].x + sigf(zi0) * tanhfast(zg0);
            float c1 = sigf(zf1) * cst[bb].y + sigf(zi1) * tanhfast(zg1);
            cst[bb] = make_float2(c0, c1);
            float h0 = sigf(zo0) * tanhfast(c0);
            float h1 = sigf(zo1) * tanhfast(c1);
            int r = r0 + bb;
            __stcg(reinterpret_cast<float2*>(hWrite + (size_t)r * HH + ngl),
                   make_float2(h0, h1));
            if (write_seq)
                *reinterpret_cast<float2*>(
                    g_seq + ((size_t)t * BB + r) * (2 * HH) + dir * HH + nloc + nt * 32) =
                    make_float2(h0, h1);
        }

        grid_bar(epoch);
    }
}

// ---------------- final dense + softmax ----------------
__global__ void final_k(const float* __restrict__ Wd, const float* __restrict__ bd,
                        float* __restrict__ out)
{
    int b = blockIdx.x, lane = threadIdx.x;
    const float* hf = g_state;
    const float* hb = g_state + 2 * BB * HH;
    float acc[CC];
#pragma unroll
    for (int c = 0; c < CC; ++c) acc[c] = 0.f;
    for (int k = lane; k < 2 * HH; k += 32) {
        float hv = (k < HH) ? hf[(size_t)b * HH + k] : hb[(size_t)b * HH + k - HH];
        const float* w = Wd + (size_t)k * CC;
#pragma unroll
        for (int c = 0; c < CC; ++c) acc[c] = fmaf(hv, w[c], acc[c]);
    }
#pragma unroll
    for (int c = 0; c < CC; ++c)
#pragma unroll
        for (int o = 16; o; o >>= 1) acc[c] += __shfl_down_sync(0xffffffffu, acc[c], o);
    if (lane == 0) {
        float m = -1e30f;
#pragma unroll
        for (int c = 0; c < CC; ++c) { acc[c] += bd[c]; m = fmaxf(m, acc[c]); }
        float e[CC], s = 0.f;
#pragma unroll
        for (int c = 0; c < CC; ++c) { e[c] = expf(acc[c] - m); s += e[c]; }
        float inv = 1.f / s;
#pragma unroll
        for (int c = 0; c < CC; ++c) out[b * CC + c] = e[c] * inv;
    }
}

extern "C" void kernel_launch(void* const* d_in, const int* in_sizes, int n_in,
                              void* d_out, int out_size)
{
    const int*   x   = (const int*)  d_in[0];
    const float* emb = (const float*)d_in[1];
    const float* W1f = (const float*)d_in[2];
    const float* U1f = (const float*)d_in[3];
    const float* b1f = (const float*)d_in[4];
    const float* W1b = (const float*)d_in[5];
    const float* U1b = (const float*)d_in[6];
    const float* b1b = (const float*)d_in[7];
    const float* W2f = (const float*)d_in[8];
    const float* U2f = (const float*)d_in[9];
    const float* b2f = (const float*)d_in[10];
    const float* W2b = (const float*)d_in[11];
    const float* U2b = (const float*)d_in[12];
    const float* b2b = (const float*)d_in[13];
    const float* Wd  = (const float*)d_in[14];
    const float* bd  = (const float*)d_in[15];
    float* out = (float*)d_out;

    static int smem_set = 0;
    if (!smem_set) {
        cudaFuncSetAttribute(lstm_persist_k,
                             cudaFuncAttributeMaxDynamicSharedMemorySize, 131072);
        smem_set = 1;
    }

    embed_k<<<(MROWS * 32) / 256, 256>>>(x, emb);

    dim3 gg(MROWS / 128, G4 / 128);

    // layer 1
    gemm_k<<<gg, 256>>>(0, 0, W1f, b1f, DD);
    gemm_k<<<gg, 256>>>(0, 1, W1b, b1b, DD);
    lstm_persist_k<<<NCTA, 128, 131072>>>(U1f, U1b, 1);

    // layer 2
    gemm_k<<<gg, 256>>>(1, 0, W2f, b2f, 2 * HH);
    gemm_k<<<gg, 256>>>(1, 1, W2b, b2b, 2 * HH);
    lstm_persist_k<<<NCTA, 128, 131072>>>(U2f, U2b, 0);

    final_k<<<BB, 32>>>(Wd, bd, out);
}

// round 7
// speedup vs baseline: 1.1684x; 1.0447x over previous
#include <cuda_runtime.h>
#include <math.h>

#define TT 512
#define BB 128
#define DD 128
#define HH 256
#define CC 10
#define G4 1024
#define MROWS (TT*BB)
#define NCTA 128
#define NGRP 8            // CTAs per barrier group = one (dir, batch-tile)

// ---------------- static device scratch (no runtime allocation) ----------------
__device__ float g_e  [(size_t)MROWS * DD];        //  32 MB embedded inputs [t*B+b, D]
__device__ float g_XwF[(size_t)MROWS * G4];        // 256 MB x@W fwd (reused layer 2)
__device__ float g_XwB[(size_t)MROWS * G4];        // 256 MB x@W bwd (reused layer 2)
__device__ float g_seq[(size_t)MROWS * 2 * HH];    // 128 MB layer-1 output sequence
__device__ float g_state[4 * BB * HH];             // per dir: h parity buf0, buf1
__device__ unsigned g_bcount[16 * 32];             // per-group arrive counters (128B apart)
__device__ unsigned g_bepoch[16 * 32];             // per-group epochs (128B apart)

// packed dual-fp32 FMA (recurrence inner loop)
__device__ __forceinline__ void ffma2(float2 &d, float2 a, float2 b) {
    asm("fma.rn.f32x2 %0, %1, %2, %0;"
        : "+l"(*reinterpret_cast<unsigned long long*>(&d))
        : "l"(*reinterpret_cast<unsigned long long*>(&a)),
          "l"(*reinterpret_cast<unsigned long long*>(&b)));
}

__device__ __forceinline__ float sigf(float x) {
    return __fdividef(1.0f, 1.0f + __expf(-x));
}
__device__ __forceinline__ float tanhfast(float x) {
    return __fdividef(2.0f, 1.0f + __expf(-2.0f * x)) - 1.0f;
}

// cp.async 16B: GMEM -> SMEM without register staging
__device__ __forceinline__ void cpa16(unsigned dst, const void* src) {
    asm volatile("cp.async.cg.shared.global [%0], [%1], 16;" :: "r"(dst), "l"(src));
}
#define CPA_COMMIT() asm volatile("cp.async.commit_group;")
#define CPA_WAIT0()  asm volatile("cp.async.wait_group 0;")

// fp32 -> tf32 (round to nearest, kept in b32 reg)
__device__ __forceinline__ unsigned f2tf32(float x) {
    unsigned r; asm("cvt.rna.tf32.f32 %0, %1;" : "=r"(r) : "f"(x)); return r;
}

// m16n8k8 tf32 MMA, fp32 accumulate (D += A*B)
__device__ __forceinline__ void mma_tf32(float* c, const unsigned* a, const unsigned* b) {
    asm("mma.sync.aligned.m16n8k8.row.col.f32.tf32.tf32.f32 "
        "{%0,%1,%2,%3}, {%4,%5,%6,%7}, {%8,%9}, {%0,%1,%2,%3};"
        : "+f"(c[0]), "+f"(c[1]), "+f"(c[2]), "+f"(c[3])
        : "r"(a[0]), "r"(a[1]), "r"(a[2]), "r"(a[3]), "r"(b[0]), "r"(b[1]));
}

// per-group software barrier: 8 CTAs sharing one (dir, batch-tile)
__device__ __forceinline__ void grid_bar(int grp, unsigned &epoch) {
    __threadfence();
    __syncthreads();
    if (threadIdx.x == 0) {
        unsigned* cnt = &g_bcount[grp * 32];
        unsigned* ep  = &g_bepoch[grp * 32];
        if (atomicAdd(cnt, 1) == NGRP - 1) {
            atomicExch(cnt, 0);
            __threadfence();
            atomicAdd(ep, 1);
        } else {
            while (*(volatile unsigned*)ep == epoch) { }
        }
        epoch++;
    }
    __syncthreads();
}

// ---------------- embedding gather: g_e[t*B+b, :] = emb[x[b,t], :] ----------------
__global__ void embed_k(const int* __restrict__ x, const float* __restrict__ emb) {
    int gid = blockIdx.x * blockDim.x + threadIdx.x;
    int r  = gid >> 5;
    int c4 = gid & 31;
    int t  = r >> 7;
    int b  = r & 127;
    int tok = x[b * TT + t];
    reinterpret_cast<float4*>(g_e)[(size_t)r * 32 + c4] =
        reinterpret_cast<const float4*>(emb)[(size_t)tok * 32 + c4];
}

// ---------------- 3xTF32 tensor-core GEMM + bias: C[M,1024] = A[M,K]@W[K,1024]+b ----
// BM=BN=128 BK=16, 256 threads = 8 warps (4 M x 2 N), warp tile 32x64.
// fp32 tiles in smem (cp.async double-buffered); hi/lo tf32 split in registers;
// 3 MMAs (hh, hl, lh) per fragment pair -> fp32-level accuracy on tensor pipe.
#define AS_LD 20     // A smem row stride (bank-conflict-free for frag pattern)
#define BS_LD 136    // B smem row stride
__global__ __launch_bounds__(256) void gemm_k(int a_sel, int c_sel,
        const float* __restrict__ W, const float* __restrict__ bias, int K)
{
    const float* A = a_sel ? g_seq : g_e;
    float*       C = c_sel ? g_XwB : g_XwF;

    __shared__ __align__(16) float As[2][128][AS_LD];
    __shared__ __align__(16) float Bs[2][16][BS_LD];

    const int m0   = blockIdx.x * 128;
    const int n0   = blockIdx.y * 128;
    const int tid  = threadIdx.x;
    const int lane = tid & 31;
    const int warp = tid >> 5;
    const int gid  = lane >> 2;     // 0..7
    const int tig  = lane & 3;      // 0..3
    const int wm   = warp & 3;      // M warp: rows wm*32..+32
    const int wn   = warp >> 2;     // N warp: cols wn*64..+64

    const unsigned sA = (unsigned)__cvta_generic_to_shared(&As[0][0][0]);
    const unsigned sB = (unsigned)__cvta_generic_to_shared(&Bs[0][0][0]);
    const unsigned bufA = 128 * AS_LD * 4;
    const unsigned bufB = 16 * BS_LD * 4;

    float acc[2][8][4];
#pragma unroll
    for (int mb = 0; mb < 2; ++mb)
#pragma unroll
        for (int nb = 0; nb < 8; ++nb)
#pragma unroll
            for (int r = 0; r < 4; ++r) acc[mb][nb][r] = 0.f;

    const int nk = K >> 4;

    // tile loader: A 128x16 (512 chunks), B 16x128 (512 chunks), 2+2 per thread
    auto load_tile = [&](int buf, int kt) {
#pragma unroll
        for (int i = 0; i < 2; ++i) {
            int id = tid + i * 256;
            int r = id >> 2, kq = id & 3;
            cpa16(sA + buf * bufA + (unsigned)((r * AS_LD + kq * 4) * 4),
                  A + (size_t)(m0 + r) * K + kt + kq * 4);
        }
#pragma unroll
        for (int i = 0; i < 2; ++i) {
            int id = tid + i * 256;
            int r = id >> 5, c4 = (id & 31) * 4;
            cpa16(sB + buf * bufB + (unsigned)((r * BS_LD + c4) * 4),
                  W + (size_t)(kt + r) * G4 + n0 + c4);
        }
        CPA_COMMIT();
    };

    load_tile(0, 0);
    CPA_WAIT0();
    __syncthreads();

    for (int kt = 0; kt < nk; ++kt) {
        const int cur = kt & 1;
        const bool more = (kt + 1) < nk;
        if (more) load_tile(cur ^ 1, (kt + 1) << 4);

#pragma unroll
        for (int kh = 0; kh < 2; ++kh) {
            const int k0 = kh * 8;
            // A fragments (2 M-blocks), tf32 hi/lo
            unsigned ahi[2][4], alo[2][4];
#pragma unroll
            for (int mb = 0; mb < 2; ++mb) {
                const int rbase = wm * 32 + mb * 16 + gid;
#pragma unroll
                for (int r = 0; r < 4; ++r) {
                    float v = As[cur][rbase + (r & 1) * 8][k0 + tig + (r >> 1) * 4];
                    unsigned h = f2tf32(v);
                    ahi[mb][r] = h;
                    alo[mb][r] = f2tf32(v - __uint_as_float(h));
                }
            }
#pragma unroll
            for (int nb = 0; nb < 8; ++nb) {
                const int nc = wn * 64 + nb * 8 + gid;
                float b0 = Bs[cur][k0 + tig][nc];
                float b1 = Bs[cur][k0 + tig + 4][nc];
                unsigned bh[2], bl[2];
                bh[0] = f2tf32(b0); bl[0] = f2tf32(b0 - __uint_as_float(bh[0]));
                bh[1] = f2tf32(b1); bl[1] = f2tf32(b1 - __uint_as_float(bh[1]));
#pragma unroll
                for (int mb = 0; mb < 2; ++mb) mma_tf32(acc[mb][nb], ahi[mb], bh);
#pragma unroll
                for (int mb = 0; mb < 2; ++mb) mma_tf32(acc[mb][nb], ahi[mb], bl);
#pragma unroll
                for (int mb = 0; mb < 2; ++mb) mma_tf32(acc[mb][nb], alo[mb], bh);
            }
        }
        if (more) {
            CPA_WAIT0();
            __syncthreads();
        }
    }

    // epilogue: + bias, store (c0,c1)->row, (c2,c3)->row+8
#pragma unroll
    for (int mb = 0; mb < 2; ++mb) {
        const int row0 = m0 + wm * 32 + mb * 16 + gid;
#pragma unroll
        for (int nb = 0; nb < 8; ++nb) {
            const int col = n0 + wn * 64 + nb * 8 + tig * 2;
            float2 bv = *reinterpret_cast<const float2*>(bias + col);
            float2 v0 = make_float2(acc[mb][nb][0] + bv.x, acc[mb][nb][1] + bv.y);
            float2 v1 = make_float2(acc[mb][nb][2] + bv.x, acc[mb][nb][3] + bv.y);
            *reinterpret_cast<float2*>(C + (size_t)row0 * G4 + col)       = v0;
            *reinterpret_cast<float2*>(C + (size_t)(row0 + 8) * G4 + col) = v1;
        }
    }
}

// ---------------- persistent bidirectional LSTM layer ----------------
// bid = dir*64 + bt*8 + nt  (group = bid>>3 = dir*8+bt: the 8 CTAs sharing a
// batch tile; only they exchange h, so the barrier spans 8 CTAs).
__global__ __launch_bounds__(128) void lstm_persist_k(
        const float* __restrict__ Uf, const float* __restrict__ Ub, int write_seq)
{
    extern __shared__ float Us[];                 // [256][128] U slice
    __shared__ __align__(16) float sh[16][260];   // h tile stage

    const int bid = blockIdx.x;
    const int dir = bid >> 6;
    const int bt  = (bid >> 3) & 7;
    const int nt  = bid & 7;
    const int grp = bid >> 3;                     // 0..15
    const int tid = threadIdx.x;

    const float* U  = dir ? Ub : Uf;
    const float* Xw = dir ? g_XwB : g_XwF;
    float* hbuf = g_state + (size_t)dir * 2 * BB * HH;

    // load U slice: Us[k*128 + g*32 + ln] = U[k*G4 + g*HH + nt*32 + ln]
    for (int i = tid; i < 256 * 32; i += 128) {
        int k = i >> 5;
        int col = (i & 31) * 4;
        int g = col >> 5, ln = col & 31;
        *reinterpret_cast<float4*>(&Us[k * 128 + col]) =
            *reinterpret_cast<const float4*>(U + (size_t)k * G4 + g * HH + nt * 32 + ln);
    }

    // zero my (bt, nt) patch of both h parity buffers
    for (int i = tid; i < 512; i += 128) {
        int r  = bt * 16 + (i >> 5);
        int cc = nt * 32 + (i & 31);
        __stcg(hbuf + (size_t)r * HH + cc, 0.f);
        __stcg(hbuf + (size_t)BB * HH + (size_t)r * HH + cc, 0.f);
    }

    unsigned epoch = 0;
    if (tid == 0) epoch = *(volatile unsigned*)&g_bepoch[grp * 32];
    grid_bar(grp, epoch);

    const int b_half = tid >> 4;
    const int n_grp  = tid & 15;
    const int nloc   = n_grp * 2;
    const int ngl    = nt * 32 + nloc;
    const int r0     = bt * 16 + b_half * 2;

    float2 cst[2] = {make_float2(0.f, 0.f), make_float2(0.f, 0.f)};

    for (int s = 0; s < TT; ++s) {
        const int t   = dir ? (TT - 1 - s) : s;
        const int par = s & 1;
        const float* hRead  = hbuf + (size_t)par * BB * HH;
        float*       hWrite = hbuf + (size_t)(par ^ 1) * BB * HH;

#pragma unroll
        for (int i = 0; i < 8; ++i) {
            int f = tid + i * 128;
            int r = f >> 6, cq = f & 63;
            *reinterpret_cast<float4*>(&sh[r][cq * 4]) =
                __ldcg(reinterpret_cast<const float4*>(
                    hRead + (size_t)(bt * 16 + r) * HH + cq * 4));
        }
        const float* xw0 = Xw + ((size_t)t * BB + r0) * G4 + ngl;
        const float* xw1 = xw0 + G4;
        float2 x0[4], x1[4];
#pragma unroll
        for (int g = 0; g < 4; ++g) {
            x0[g] = *reinterpret_cast<const float2*>(xw0 + g * HH);
            x1[g] = *reinterpret_cast<const float2*>(xw1 + g * HH);
        }
        __syncthreads();

        float2 acc[4][2];
#pragma unroll
        for (int g = 0; g < 4; ++g) {
            acc[g][0] = make_float2(0.f, 0.f);
            acc[g][1] = make_float2(0.f, 0.f);
        }

        const float* sr0 = sh[b_half * 2];
        const float* sr1 = sh[b_half * 2 + 1];
        const float* Up  = Us + nloc;

#pragma unroll 4
        for (int k4 = 0; k4 < HH; k4 += 4) {
            float4 h0v = *reinterpret_cast<const float4*>(sr0 + k4);
            float4 h1v = *reinterpret_cast<const float4*>(sr1 + k4);
            const float h0a[4] = {h0v.x, h0v.y, h0v.z, h0v.w};
            const float h1a[4] = {h1v.x, h1v.y, h1v.z, h1v.w};
#pragma unroll
            for (int kk = 0; kk < 4; ++kk) {
                const float* row = Up + (size_t)(k4 + kk) * 128;
                float2 hh0 = make_float2(h0a[kk], h0a[kk]);
                float2 hh1 = make_float2(h1a[kk], h1a[kk]);
#pragma unroll
                for (int g = 0; g < 4; ++g) {
                    float2 u2 = *reinterpret_cast<const float2*>(row + g * 32);
                    ffma2(acc[g][0], u2, hh0);
                    ffma2(acc[g][1], u2, hh1);
                }
            }
        }

#pragma unroll
        for (int bb = 0; bb < 2; ++bb) {
            const float2* xg = bb ? x1 : x0;
            float zi0 = acc[0][bb].x + xg[0].x, zi1 = acc[0][bb].y + xg[0].y;
            float zf0 = acc[1][bb].x + xg[1].x, zf1 = acc[1][bb].y + xg[1].y;
            float zg0 = acc[2][bb].x + xg[2].x, zg1 = acc[2][bb].y + xg[2].y;
            float zo0 = acc[3][bb].x + xg[3].x, zo1 = acc[3][bb].y + xg[3].y;
            float c0 = sigf(zf0) * cst[bb].x + sigf(zi0) * tanhfast(zg0);
            float c1 = sigf(zf1) * cst[bb].y + sigf(zi1) * tanhfast(zg1);
            cst[bb] = make_float2(c0, c1);
            float h0 = sigf(zo0) * tanhfast(c0);
            float h1 = sigf(zo1) * tanhfast(c1);
            int r = r0 + bb;
            __stcg(reinterpret_cast<float2*>(hWrite + (size_t)r * HH + ngl),
                   make_float2(h0, h1));
            if (write_seq)
                *reinterpret_cast<float2*>(
                    g_seq + ((size_t)t * BB + r) * (2 * HH) + dir * HH + ngl) =
                    make_float2(h0, h1);
        }

        grid_bar(grp, epoch);
    }
}

// ---------------- final dense + softmax ----------------
__global__ void final_k(const float* __restrict__ Wd, const float* __restrict__ bd,
                        float* __restrict__ out)
{
    int b = blockIdx.x, lane = threadIdx.x;
    const float* hf = g_state;
    const float* hb = g_state + 2 * BB * HH;
    float acc[CC];
#pragma unroll
    for (int c = 0; c < CC; ++c) acc[c] = 0.f;
    for (int k = lane; k < 2 * HH; k += 32) {
        float hv = (k < HH) ? hf[(size_t)b * HH + k] : hb[(size_t)b * HH + k - HH];
        const float* w = Wd + (size_t)k * CC;
#pragma unroll
        for (int c = 0; c < CC; ++c) acc[c] = fmaf(hv, w[c], acc[c]);
    }
#pragma unroll
    for (int c = 0; c < CC; ++c)
#pragma unroll
        for (int o = 16; o; o >>= 1) acc[c] += __shfl_down_sync(0xffffffffu, acc[c], o);
    if (lane == 0) {
        float m = -1e30f;
#pragma unroll
        for (int c = 0; c < CC; ++c) { acc[c] += bd[c]; m = fmaxf(m, acc[c]); }
        float e[CC], s = 0.f;
#pragma unroll
        for (int c = 0; c < CC; ++c) { e[c] = expf(acc[c] - m); s += e[c]; }
        float inv = 1.f / s;
#pragma unroll
        for (int c = 0; c < CC; ++c) out[b * CC + c] = e[c] * inv;
    }
}

extern "C" void kernel_launch(void* const* d_in, const int* in_sizes, int n_in,
                              void* d_out, int out_size)
{
    const int*   x   = (const int*)  d_in[0];
    const float* emb = (const float*)d_in[1];
    const float* W1f = (const float*)d_in[2];
    const float* U1f = (const float*)d_in[3];
    const float* b1f = (const float*)d_in[4];
    const float* W1b = (const float*)d_in[5];
    const float* U1b = (const float*)d_in[6];
    const float* b1b = (const float*)d_in[7];
    const float* W2f = (const float*)d_in[8];
    const float* U2f = (const float*)d_in[9];
    const float* b2f = (const float*)d_in[10];
    const float* W2b = (const float*)d_in[11];
    const float* U2b = (const float*)d_in[12];
    const float* b2b = (const float*)d_in[13];
    const float* Wd  = (const float*)d_in[14];
    const float* bd  = (const float*)d_in[15];
    float* out = (float*)d_out;

    static int smem_set = 0;
    if (!smem_set) {
        cudaFuncSetAttribute(lstm_persist_k,
                             cudaFuncAttributeMaxDynamicSharedMemorySize, 131072);
        smem_set = 1;
    }

    embed_k<<<(MROWS * 32) / 256, 256>>>(x, emb);

    dim3 gg(MROWS / 128, G4 / 128);

    // layer 1
    gemm_k<<<gg, 256>>>(0, 0, W1f, b1f, DD);
    gemm_k<<<gg, 256>>>(0, 1, W1b, b1b, DD);
    lstm_persist_k<<<NCTA, 128, 131072>>>(U1f, U1b, 1);

    // layer 2
    gemm_k<<<gg, 256>>>(1, 0, W2f, b2f, 2 * HH);
    gemm_k<<<gg, 256>>>(1, 1, W2b, b2b, 2 * HH);
    lstm_persist_k<<<NCTA, 128, 131072>>>(U2f, U2b, 0);

    final_k<<<BB, 32>>>(Wd, bd, out);
}